// round 15
// baseline (speedup 1.0000x reference)
#include <cuda_runtime.h>
#include <math.h>

#define NB   32      // batch
#define NC   512     // channels
#define HW   4096    // 64*64
#define NSEG 129     // segment ids 0..128 (0 dropped later)
#define NSG  128     // kept segments
#define NCLS 19
#define ATTH 512
#define MTOT (NB * NSG)   // 4096 GEMM rows
#define NTILE 32          // 128-pixel tiles per batch

// ---- scratch (device globals; no allocation allowed) ----
__device__ int   g_cnt[NB * NSEG];
__device__ float g_invc[NB * NSEG];
__device__ int   g_sorted[NB * HW];          // per tile: 128 packed ((id*66)<<16 | pos*66)
__device__ int   g_toff[NB * NTILE * 16];    // per tile: 16 warp start offsets
__device__ float g_meansT[NC * MTOT];        // [c][m]: GEMM A (m-contig) + wm reads
__device__ float g_att[MTOT];

__device__ __forceinline__ unsigned f2tf(float f) {
    unsigned u; asm("cvt.rna.tf32.f32 %0, %1;" : "=r"(u) : "f"(f)); return u;
}

#define MMA_TF32(d, a, b0_, b1_) \
    asm volatile("mma.sync.aligned.m16n8k8.row.col.f32.tf32.tf32.f32 " \
        "{%0,%1,%2,%3}, {%4,%5,%6,%7}, {%8,%9}, {%0,%1,%2,%3};" \
        : "+f"(d[0]), "+f"(d[1]), "+f"(d[2]), "+f"(d[3]) \
        : "r"(a[0]), "r"(a[1]), "r"(a[2]), "r"(a[3]), "r"(b0_), "r"(b1_))

// ============================================================
// Kernel 0: zero counters / att accumulator, init out = bh.
// ============================================================
__global__ void zero_kernel(const float* __restrict__ bh,
                            float* __restrict__ out) {
    int t = blockIdx.x * 256 + threadIdx.x;   // grid 17 -> 4352
    if (t < MTOT) g_att[t] = 0.0f;
    if (t < NB * NSEG) g_cnt[t] = 0;
    if (t < NB * NCLS) out[t] = bh[t % NCLS];
}

// ============================================================
// Kernel 1: downsample + per-tile counting sort of segment ids.
// Packed sorted entries ((id*66)<<16 | pos*66) -- premultiplied
// for the 66-word (64ch float2) tile rows of seg_kernel.
// Parallel shfl prefix scan over the 129 bins.
// ============================================================
__global__ void prep_sort_kernel(const int* __restrict__ mask) {
    int b = blockIdx.y, tile = blockIdx.x;
    int t = threadIdx.x;
    int lane = t & 31, w = t >> 5;
    __shared__ int hist[NSEG];
    __shared__ int pref[NSEG];
    __shared__ int sid[128];
    __shared__ int wsum[4];

    for (int i = t; i < NSEG; i += 128) hist[i] = 0;
    __syncthreads();

    int p = tile * 128 + t;
    int i = p >> 6, j = p & 63;
    int id = mask[((long long)b * 512 + i * 8) * 512 + j * 8];
    id = min(max(id, 0), NSEG - 1);
    sid[t] = id;
    atomicAdd(&hist[id], 1);
    __syncthreads();

    // parallel exclusive scan of hist[0..128] -> pref
    int v = hist[t];
    #pragma unroll
    for (int o = 1; o < 32; o <<= 1) {
        int n = __shfl_up_sync(0xffffffffu, v, o);
        if (lane >= o) v += n;
    }
    if (lane == 31) wsum[w] = v;
    __syncthreads();
    if (t == 0) {
        int s = 0;
        #pragma unroll
        for (int k = 0; k < 4; ++k) { int xv = wsum[k]; wsum[k] = s; s += xv; }
    }
    __syncthreads();
    int incl = v + wsum[w];
    pref[t] = incl - hist[t];
    if (t == 127) pref[128] = incl;
    __syncthreads();

    for (int k = t; k < NSEG; k += 128)
        if (hist[k]) atomicAdd(&g_cnt[b * NSEG + k], hist[k]);
    if (t < 16) g_toff[(b * NTILE + tile) * 16 + t] = pref[t * 8];
    __syncthreads();   // toff reads done before pref is mutated

    int rank = atomicAdd(&pref[sid[t]], 1);
    g_sorted[(b * NTILE + tile) * 128 + rank] = ((sid[t] * 66) << 16) | (t * 66);
}

// ============================================================
// Kernel 2 (tiny): counts -> inverse counts.
// ============================================================
__global__ void invc_kernel() {
    int t = threadIdx.x;   // 160 threads, grid NB
    int b = blockIdx.x;
    if (t < NSEG) {
        int cv = g_cnt[b * NSEG + t];
        g_invc[b * NSEG + t] = (t >= 1 && cv > 0) ? (1.0f / (float)cv) : 0.0f;
    }
}

// ============================================================
// Kernel 3: segment sums — 64 CHANNELS per block, float2 smem
// payload (LDS.64/STS.64). Lane = channel-pair; tile row = 66
// words (64ch + pad). Same crossbar bytes as the 32-ch version
// but HALF the scatter iterations / address ALU / s_sorted
// loads / blocks (grid 256 = single wave at 2 blocks/SM).
// Double-buffered tile, one barrier per tile. Warp w (of 16)
// owns ids [8w, 8w+8) -> race-free single accumulator.
// ============================================================
#define TILE_W2 66
#define SEG_SMEM ((2 * 128 * TILE_W2 + NSEG * TILE_W2) * 4)

__global__ void __launch_bounds__(512, 2)
seg_kernel(const float* __restrict__ x) {
    extern __shared__ float sseg[];
    float* s_tile = sseg;                        // 2 x [128 pos][66]
    float* s_acc  = sseg + 2 * 128 * TILE_W2;    // [129 id][66]
    __shared__ int s_sorted[2][128];
    __shared__ int s_off[2][16];
    __shared__ float s_invc[NSEG];

    int b = blockIdx.y;
    int cbase = blockIdx.x * 64;
    int tid = threadIdx.x;
    int w = tid >> 5, lane = tid & 31;

    for (int t = tid; t < NSEG * TILE_W2; t += 512) s_acc[t] = 0.0f;
    for (int t = tid; t < NSEG; t += 512) s_invc[t] = g_invc[b * NSEG + t];

    int cf = tid >> 3, qf = tid & 7;    // staging: channel cf (0..63), f4-slot qf(+8k)
    const float4* xp = (const float4*)x + (long long)(b * NC + cbase + cf) * (HW / 4);
    const int* sortb = g_sorted + (long long)b * HW;
    const int* toffb = g_toff + b * NTILE * 16;

    // prefetch tile 0 (4 float4 per thread = 16 pixels of channel cf)
    float4 pf[4];
    int rsort = 0, roff = 0;
    #pragma unroll
    for (int k = 0; k < 4; ++k) pf[k] = xp[qf + 8 * k];
    if (tid < 128) rsort = sortb[tid];
    if (tid < 16)  roff  = toffb[tid];

    #pragma unroll 1
    for (int tile = 0; tile < NTILE; ++tile) {
        int buf = tile & 1;
        // 1) stage tile (pf regs) into buf: [pos][ch] rows of 66 words
        float* tb = s_tile + buf * 128 * TILE_W2;
        #pragma unroll
        for (int k = 0; k < 4; ++k) {
            int f4 = qf + 8 * k;
            float* o = tb + (f4 * 4) * TILE_W2 + cf;
            o[0] = pf[k].x; o[TILE_W2] = pf[k].y;
            o[2 * TILE_W2] = pf[k].z; o[3 * TILE_W2] = pf[k].w;
        }
        if (tid < 128) s_sorted[buf][tid] = rsort;
        if (tid < 16)  s_off[buf][tid]    = roff;

        // 2) issue global loads for tile+1 (overlaps scatter)
        if (tile + 1 < NTILE) {
            #pragma unroll
            for (int k = 0; k < 4; ++k) pf[k] = xp[(tile + 1) * 32 + qf + 8 * k];
            if (tid < 128) rsort = sortb[(tile + 1) * 128 + tid];
            if (tid < 16)  roff  = toffb[(tile + 1) * 16 + tid];
        }

        // 3) scatter PREVIOUS tile (float2 per lane = 2 channels)
        if (tile > 0) {
            int pb_ = buf ^ 1;
            const float* tp = s_tile + pb_ * 128 * TILE_W2;
            int e   = s_off[pb_][w];
            int end = (w == 15) ? 128 : s_off[pb_][w + 1];
            #pragma unroll 4
            for (; e < end; ++e) {
                int s = s_sorted[pb_][e];
                float2* a = (float2*)(s_acc + (s >> 16) + 2 * lane);
                const float2* v = (const float2*)(tp + (s & 0xffff) + 2 * lane);
                float2 av = *a, vv = *v;
                av.x += vv.x; av.y += vv.y;
                *a = av;
            }
        }
        __syncthreads();
    }
    // scatter the last tile
    {
        int pb_ = (NTILE - 1) & 1;
        const float* tp = s_tile + pb_ * 128 * TILE_W2;
        int e   = s_off[pb_][w];
        int end = (w == 15) ? 128 : s_off[pb_][w + 1];
        #pragma unroll 4
        for (; e < end; ++e) {
            int s = s_sorted[pb_][e];
            float2* a = (float2*)(s_acc + (s >> 16) + 2 * lane);
            const float2* v = (const float2*)(tp + (s & 0xffff) + 2 * lane);
            float2 av = *a, vv = *v;
            av.x += vv.x; av.y += vv.y;
            *a = av;
        }
    }
    __syncthreads();

    // write meansT [c][m] (coalesced over segment); c = 0..63
    for (int t = tid; t < NSG * 64; t += 512) {
        int sm1 = t & 127, c = t >> 7;
        g_meansT[(long long)(cbase + c) * MTOT + b * NSG + sm1] =
            s_acc[(sm1 + 1) * TILE_W2 + c] * s_invc[sm1 + 1];
    }
}

// ============================================================
// Kernel 4: att logits GEMM via tf32 mma.sync. (Unchanged R13.)
// ============================================================
#define GBM 128
#define GBN 64
#define GBK 32
#define ASTR 136
#define BSTR 72
#define GEMM_SMEM ((2 * GBK * ASTR + 2 * GBK * BSTR) * 4)

__global__ void __launch_bounds__(256, 2)
att_gemm_kernel(const float* __restrict__ Wa1,
                const float* __restrict__ ba1,
                const float* __restrict__ Wa2) {
    extern __shared__ unsigned smu[];
    unsigned* sA = smu;                        // 2 x 32x136 (tf32 bits)
    unsigned* sB = smu + 2 * GBK * ASTR;       // 2 x 32x72
    __shared__ float s_b1[GBN], s_w2[GBN];

    int tid = threadIdx.x;
    int mbase = blockIdx.y * GBM;
    int nbase = blockIdx.x * GBN;
    int lane = tid & 31, wid = tid >> 5;
    int grp = lane >> 2, tig = lane & 3;
    int wm_ = (wid & 3) * 32;    // warp m offset in tile
    int wn_ = (wid >> 2) * 32;   // warp n offset in tile

    if (tid < GBN) { s_b1[tid] = ba1[nbase + tid]; s_w2[tid] = Wa2[nbase + tid]; }

    int am = tid & 31, akr = tid >> 5;
    int br = tid >> 4, bc = (tid & 15) * 4;
    const float* Ag = g_meansT + (long long)akr * MTOT + mbase + am * 4;
    const float* Bg = Wa1 + (long long)br * ATTH + nbase + bc;

    float d[2][4][4];
    #pragma unroll
    for (int mt = 0; mt < 2; ++mt)
        #pragma unroll
        for (int nt = 0; nt < 4; ++nt)
            #pragma unroll
            for (int c = 0; c < 4; ++c) d[mt][nt][c] = 0.0f;

    float4 pa[4], pb[2];
    #pragma unroll
    for (int p = 0; p < 4; ++p) pa[p] = *(const float4*)(Ag + (long long)(8 * p) * MTOT);
    #pragma unroll
    for (int p = 0; p < 2; ++p) pb[p] = *(const float4*)(Bg + (long long)(16 * p) * ATTH);

    const int NITER = NC / GBK;   // 16
    int cur = 0;
    #pragma unroll 1
    for (int it = 0; it < NITER; ++it) {
        unsigned* Ac = sA + cur * GBK * ASTR;
        unsigned* Bc = sB + cur * GBK * BSTR;
        #pragma unroll
        for (int p = 0; p < 4; ++p) {
            uint4 v = { f2tf(pa[p].x), f2tf(pa[p].y), f2tf(pa[p].z), f2tf(pa[p].w) };
            *(uint4*)(Ac + (akr + 8 * p) * ASTR + am * 4) = v;
        }
        #pragma unroll
        for (int p = 0; p < 2; ++p) {
            uint4 v = { f2tf(pb[p].x), f2tf(pb[p].y), f2tf(pb[p].z), f2tf(pb[p].w) };
            *(uint4*)(Bc + (br + 16 * p) * BSTR + bc) = v;
        }
        __syncthreads();

        if (it + 1 < NITER) {
            long long k0n = (long long)(it + 1) * GBK;
            #pragma unroll
            for (int p = 0; p < 4; ++p)
                pa[p] = *(const float4*)(Ag + (k0n + 8 * p) * MTOT);
            #pragma unroll
            for (int p = 0; p < 2; ++p)
                pb[p] = *(const float4*)(Bg + (k0n + 16 * p) * ATTH);
        }

        #pragma unroll
        for (int ks = 0; ks < 4; ++ks) {
            const unsigned* Ak  = Ac + (ks * 8 + tig) * ASTR + wm_ + grp;
            const unsigned* Ak4 = Ak + 4 * ASTR;
            unsigned a0[4] = { Ak[0],  Ak[8],  Ak4[0],  Ak4[8]  };
            unsigned a1[4] = { Ak[16], Ak[24], Ak4[16], Ak4[24] };
            const unsigned* Bk  = Bc + (ks * 8 + tig) * BSTR + wn_ + grp;
            const unsigned* Bk4 = Bk + 4 * BSTR;
            #pragma unroll
            for (int nt = 0; nt < 4; ++nt) {
                unsigned b0 = Bk[nt * 8], b1 = Bk4[nt * 8];
                MMA_TF32(d[0][nt], a0, b0, b1);
                MMA_TF32(d[1][nt], a1, b0, b1);
            }
        }
        cur ^= 1;
    }

    #pragma unroll
    for (int mt = 0; mt < 2; ++mt) {
        float p0 = 0.0f, p1 = 0.0f;
        #pragma unroll
        for (int nt = 0; nt < 4; ++nt) {
            int n0 = wn_ + nt * 8 + 2 * tig;
            float b10 = s_b1[n0], b11 = s_b1[n0 + 1];
            float w20 = s_w2[n0], w21 = s_w2[n0 + 1];
            p0 += fmaxf(d[mt][nt][0] + b10, 0.0f) * w20
                + fmaxf(d[mt][nt][1] + b11, 0.0f) * w21;
            p1 += fmaxf(d[mt][nt][2] + b10, 0.0f) * w20
                + fmaxf(d[mt][nt][3] + b11, 0.0f) * w21;
        }
        p0 += __shfl_xor_sync(0xffffffffu, p0, 1);
        p0 += __shfl_xor_sync(0xffffffffu, p0, 2);
        p1 += __shfl_xor_sync(0xffffffffu, p1, 1);
        p1 += __shfl_xor_sync(0xffffffffu, p1, 2);
        if (tig == 0) {
            atomicAdd(&g_att[mbase + wm_ + mt * 16 + grp], p0);
            atomicAdd(&g_att[mbase + wm_ + mt * 16 + grp + 8], p1);
        }
    }
}

// ============================================================
// Kernel 5: fused softmax + weighted mean + partial class dots.
// ============================================================
__global__ void wm_kernel(const float* __restrict__ Wh,
                          const float* __restrict__ ba2,
                          float* __restrict__ out) {
    int b = blockIdx.y, cg = blockIdx.x, t = threadIdx.x;
    int lane = t & 31, w = t >> 5;
    __shared__ float satt[NSG];
    __shared__ float red[4];

    float v = g_att[b * NSG + t] + ba2[0];
    float m = v;
    #pragma unroll
    for (int o = 16; o > 0; o >>= 1) m = fmaxf(m, __shfl_xor_sync(0xffffffffu, m, o));
    if (lane == 0) red[w] = m;
    __syncthreads();
    m = fmaxf(fmaxf(red[0], red[1]), fmaxf(red[2], red[3]));
    float e = expf(v - m);
    float s = e;
    #pragma unroll
    for (int o = 16; o > 0; o >>= 1) s += __shfl_xor_sync(0xffffffffu, s, o);
    __syncthreads();
    if (lane == 0) red[w] = s;
    __syncthreads();
    s = red[0] + red[1] + red[2] + red[3];
    satt[t] = e / s;
    __syncthreads();

    int c = cg * 128 + t;
    float wm = 0.0f;
    const float* mp = g_meansT + (long long)c * MTOT + b * NSG;
    #pragma unroll 8
    for (int sg = 0; sg < NSG; ++sg) wm += satt[sg] * mp[sg];

    const float* whr = Wh + (long long)c * NCLS;
    #pragma unroll 1
    for (int cls = 0; cls < NCLS; ++cls) {
        float p = wm * whr[cls];
        #pragma unroll
        for (int o = 16; o > 0; o >>= 1) p += __shfl_xor_sync(0xffffffffu, p, o);
        if (lane == 0) atomicAdd(&out[b * NCLS + cls], p);
    }
}

// ============================================================
// Kernel 6: BCE-with-logits loss, mean over all 608 elements.
// ============================================================
__global__ void loss_kernel(const float* __restrict__ target,
                            float* __restrict__ out, int out_size) {
    const int n = NB * NCLS;   // 608
    int t = threadIdx.x;
    float v = 0.0f;
    if (t < n) {
        float l = out[t];
        float tg = target[t];
        v = fmaxf(l, 0.0f) - l * tg + log1pf(expf(-fabsf(l)));
    }
    __shared__ float red[32];
    int lane = t & 31, warp = t >> 5;
    #pragma unroll
    for (int o = 16; o > 0; o >>= 1) v += __shfl_xor_sync(0xffffffffu, v, o);
    if (lane == 0) red[warp] = v;
    __syncthreads();
    if (t < 32) {
        float s = (t < 20) ? red[t] : 0.0f;
        #pragma unroll
        for (int o = 16; o > 0; o >>= 1) s += __shfl_xor_sync(0xffffffffu, s, o);
        if (t == 0) out[out_size - 1] = s / (float)n;
    }
}

// ============================================================
extern "C" void kernel_launch(void* const* d_in, const int* in_sizes, int n_in,
                              void* d_out, int out_size) {
    const float* x      = (const float*)d_in[0];
    const int*   mask   = (const int*)d_in[1];
    const float* target = (const float*)d_in[2];
    const float* Wa1    = (const float*)d_in[3];
    const float* ba1    = (const float*)d_in[4];
    const float* Wa2    = (const float*)d_in[5];
    const float* ba2    = (const float*)d_in[6];
    const float* Wh     = (const float*)d_in[7];
    const float* bh     = (const float*)d_in[8];
    float* out = (float*)d_out;

    cudaFuncSetAttribute(seg_kernel,
                         cudaFuncAttributeMaxDynamicSharedMemorySize, SEG_SMEM);
    cudaFuncSetAttribute(att_gemm_kernel,
                         cudaFuncAttributeMaxDynamicSharedMemorySize, GEMM_SMEM);

    zero_kernel<<<17, 256>>>(bh, out);                                   // idx 0
    prep_sort_kernel<<<dim3(NTILE, NB), 128>>>(mask);                    // idx 1
    invc_kernel<<<NB, 160>>>();                                          // idx 2
    seg_kernel<<<dim3(8, NB), 512, SEG_SMEM>>>(x);                       // idx 3 (profiled)
    att_gemm_kernel<<<dim3(ATTH / GBN, MTOT / GBM), 256, GEMM_SMEM>>>(Wa1, ba1, Wa2); // idx 4
    wm_kernel<<<dim3(4, NB), 128>>>(Wh, ba2, out);                       // idx 5
    loss_kernel<<<1, 640>>>(target, out, out_size);                      // idx 6
}

// round 16
// speedup vs baseline: 1.0764x; 1.0764x over previous
#include <cuda_runtime.h>
#include <math.h>

#define NB   32      // batch
#define NC   512     // channels
#define HW   4096    // 64*64
#define NSEG 129     // segment ids 0..128 (0 dropped later)
#define NSG  128     // kept segments
#define NCLS 19
#define ATTH 512
#define MTOT (NB * NSG)   // 4096 GEMM rows
#define NTILE 32          // 128-pixel tiles per batch

// ---- scratch (device globals; no allocation allowed) ----
__device__ int   g_hist[NB * NTILE * NSEG];  // per-tile histograms (plain STG)
__device__ float g_invc[NB * NSEG];
__device__ int   g_sorted[NB * HW];          // per tile: 128 packed ((id*33)<<16 | pos*33)
__device__ int   g_toff[NB * NTILE * 16];    // per tile: 16 warp start offsets
__device__ float g_meansT[NC * MTOT];        // [c][m]: GEMM A (m-contig) + wm reads
__device__ float g_att[MTOT];

__device__ __forceinline__ unsigned f2tf(float f) {
    unsigned u; asm("cvt.rna.tf32.f32 %0, %1;" : "=r"(u) : "f"(f)); return u;
}

#define MMA_TF32(d, a, b0_, b1_) \
    asm volatile("mma.sync.aligned.m16n8k8.row.col.f32.tf32.tf32.f32 " \
        "{%0,%1,%2,%3}, {%4,%5,%6,%7}, {%8,%9}, {%0,%1,%2,%3};" \
        : "+f"(d[0]), "+f"(d[1]), "+f"(d[2]), "+f"(d[3]) \
        : "r"(a[0]), "r"(a[1]), "r"(a[2]), "r"(a[3]), "r"(b0_), "r"(b1_))

// ============================================================
// Kernel 1: downsample + per-tile counting sort of segment ids.
// Packed sorted entries ((id*33)<<16 | pos*33), 16 per-warp
// start offsets, and the tile's own histogram via plain STG
// (race-free -> no zero_kernel, no global atomics).
// Parallel shfl prefix scan over the 129 bins.
// ============================================================
__global__ void prep_sort_kernel(const int* __restrict__ mask) {
    int b = blockIdx.y, tile = blockIdx.x;
    int t = threadIdx.x;
    int lane = t & 31, w = t >> 5;
    __shared__ int hist[NSEG];
    __shared__ int pref[NSEG];
    __shared__ int sid[128];
    __shared__ int wsum[4];

    for (int i = t; i < NSEG; i += 128) hist[i] = 0;
    __syncthreads();

    int p = tile * 128 + t;
    int i = p >> 6, j = p & 63;
    int id = mask[((long long)b * 512 + i * 8) * 512 + j * 8];
    id = min(max(id, 0), NSEG - 1);
    sid[t] = id;
    atomicAdd(&hist[id], 1);
    __syncthreads();

    // parallel exclusive scan of hist[0..128] -> pref
    int v = hist[t];
    #pragma unroll
    for (int o = 1; o < 32; o <<= 1) {
        int n = __shfl_up_sync(0xffffffffu, v, o);
        if (lane >= o) v += n;
    }
    if (lane == 31) wsum[w] = v;
    __syncthreads();
    if (t == 0) {
        int s = 0;
        #pragma unroll
        for (int k = 0; k < 4; ++k) { int xv = wsum[k]; wsum[k] = s; s += xv; }
    }
    __syncthreads();
    int incl = v + wsum[w];
    pref[t] = incl - hist[t];
    if (t == 127) pref[128] = incl;
    __syncthreads();

    for (int k = t; k < NSEG; k += 128)
        g_hist[(b * NTILE + tile) * NSEG + k] = hist[k];
    if (t < 16) g_toff[(b * NTILE + tile) * 16 + t] = pref[t * 8];
    __syncthreads();   // toff reads done before pref is mutated

    int rank = atomicAdd(&pref[sid[t]], 1);
    g_sorted[(b * NTILE + tile) * 128 + rank] = ((sid[t] * 33) << 16) | (t * 33);
}

// ============================================================
// Kernel 2: per-batch housekeeping — sum histograms -> invc,
// zero att accumulator, init out = bh. Grid NB, 256 threads.
// ============================================================
__global__ void invc_kernel(const float* __restrict__ bh,
                            float* __restrict__ out) {
    int t = threadIdx.x;
    int b = blockIdx.x;
    if (t < NSEG) {
        int cv = 0;
        #pragma unroll 8
        for (int tile = 0; tile < NTILE; ++tile)
            cv += g_hist[(b * NTILE + tile) * NSEG + t];
        g_invc[b * NSEG + t] = (t >= 1 && cv > 0) ? (1.0f / (float)cv) : 0.0f;
    }
    if (t < NSG) g_att[b * NSG + t] = 0.0f;
    if (t < NCLS) out[b * NCLS + t] = bh[t];
}

// ============================================================
// Kernel 3: segment sums — double-buffered tile, one barrier
// per tile, sorted branchless scatter, 512 thr / 16 warps
// (warp w owns ids [8w, 8w+8)). Byte-identical to R14.
// ============================================================
#define TILE_W 33
#define SEG_SMEM ((2 * 128 * TILE_W + NSEG * TILE_W) * 4)

__global__ void __launch_bounds__(512, 3)
seg_kernel(const float* __restrict__ x) {
    extern __shared__ float sseg[];
    float* s_tile = sseg;                       // 2 x [128 pos][33]
    float* s_acc  = sseg + 2 * 128 * TILE_W;    // [129 id][33]
    __shared__ int s_sorted[2][128];
    __shared__ int s_off[2][16];
    __shared__ float s_invc[NSEG];

    int b = blockIdx.y;
    int cbase = blockIdx.x * 32;
    int tid = threadIdx.x;
    int w = tid >> 5, lane = tid & 31;

    for (int t = tid; t < NSEG * TILE_W; t += 512) s_acc[t] = 0.0f;
    for (int t = tid; t < NSEG; t += 512) s_invc[t] = g_invc[b * NSEG + t];

    int cf = tid >> 4, qf = tid & 15;   // staging: channel cf, f4-slot qf(+16k)
    const float4* xp = (const float4*)x + (long long)(b * NC + cbase + cf) * (HW / 4);
    const int* sortb = g_sorted + (long long)b * HW;
    const int* toffb = g_toff + b * NTILE * 16;

    // prefetch tile 0
    float4 pf[2];
    int rsort = 0, roff = 0;
    #pragma unroll
    for (int k = 0; k < 2; ++k) pf[k] = xp[qf + 16 * k];
    if (tid < 128) rsort = sortb[tid];
    if (tid < 16)  roff  = toffb[tid];

    #pragma unroll 1
    for (int tile = 0; tile < NTILE; ++tile) {
        int buf = tile & 1;
        float* tb = s_tile + buf * 128 * TILE_W;
        #pragma unroll
        for (int k = 0; k < 2; ++k) {
            int f4 = qf + 16 * k;
            float* o = tb + (f4 * 4) * TILE_W + cf;
            o[0] = pf[k].x; o[33] = pf[k].y; o[66] = pf[k].z; o[99] = pf[k].w;
        }
        if (tid < 128) s_sorted[buf][tid] = rsort;
        if (tid < 16)  s_off[buf][tid]    = roff;

        if (tile + 1 < NTILE) {
            #pragma unroll
            for (int k = 0; k < 2; ++k) pf[k] = xp[(tile + 1) * 32 + qf + 16 * k];
            if (tid < 128) rsort = sortb[(tile + 1) * 128 + tid];
            if (tid < 16)  roff  = toffb[(tile + 1) * 16 + tid];
        }

        if (tile > 0) {
            int pb_ = buf ^ 1;
            const float* tp = s_tile + pb_ * 128 * TILE_W;
            int e   = s_off[pb_][w];
            int end = (w == 15) ? 128 : s_off[pb_][w + 1];
            #pragma unroll 4
            for (; e < end; ++e) {
                int s = s_sorted[pb_][e];
                s_acc[(s >> 16) + lane] += tp[(s & 0xffff) + lane];
            }
        }
        __syncthreads();
    }
    {
        int pb_ = (NTILE - 1) & 1;
        const float* tp = s_tile + pb_ * 128 * TILE_W;
        int e   = s_off[pb_][w];
        int end = (w == 15) ? 128 : s_off[pb_][w + 1];
        #pragma unroll 4
        for (; e < end; ++e) {
            int s = s_sorted[pb_][e];
            s_acc[(s >> 16) + lane] += tp[(s & 0xffff) + lane];
        }
    }
    __syncthreads();

    for (int t = tid; t < NSG * 32; t += 512) {
        int sm1 = t & 127, c = t >> 7;
        g_meansT[(long long)(cbase + c) * MTOT + b * NSG + sm1] =
            s_acc[(sm1 + 1) * TILE_W + c] * s_invc[sm1 + 1];
    }
}

// ============================================================
// Kernel 4: att logits GEMM via tf32 mma.sync. (Unchanged R13.)
// ============================================================
#define GBM 128
#define GBN 64
#define GBK 32
#define ASTR 136
#define BSTR 72
#define GEMM_SMEM ((2 * GBK * ASTR + 2 * GBK * BSTR) * 4)

__global__ void __launch_bounds__(256, 2)
att_gemm_kernel(const float* __restrict__ Wa1,
                const float* __restrict__ ba1,
                const float* __restrict__ Wa2) {
    extern __shared__ unsigned smu[];
    unsigned* sA = smu;                        // 2 x 32x136 (tf32 bits)
    unsigned* sB = smu + 2 * GBK * ASTR;       // 2 x 32x72
    __shared__ float s_b1[GBN], s_w2[GBN];

    int tid = threadIdx.x;
    int mbase = blockIdx.y * GBM;
    int nbase = blockIdx.x * GBN;
    int lane = tid & 31, wid = tid >> 5;
    int grp = lane >> 2, tig = lane & 3;
    int wm_ = (wid & 3) * 32;    // warp m offset in tile
    int wn_ = (wid >> 2) * 32;   // warp n offset in tile

    if (tid < GBN) { s_b1[tid] = ba1[nbase + tid]; s_w2[tid] = Wa2[nbase + tid]; }

    int am = tid & 31, akr = tid >> 5;
    int br = tid >> 4, bc = (tid & 15) * 4;
    const float* Ag = g_meansT + (long long)akr * MTOT + mbase + am * 4;
    const float* Bg = Wa1 + (long long)br * ATTH + nbase + bc;

    float d[2][4][4];
    #pragma unroll
    for (int mt = 0; mt < 2; ++mt)
        #pragma unroll
        for (int nt = 0; nt < 4; ++nt)
            #pragma unroll
            for (int c = 0; c < 4; ++c) d[mt][nt][c] = 0.0f;

    float4 pa[4], pb[2];
    #pragma unroll
    for (int p = 0; p < 4; ++p) pa[p] = *(const float4*)(Ag + (long long)(8 * p) * MTOT);
    #pragma unroll
    for (int p = 0; p < 2; ++p) pb[p] = *(const float4*)(Bg + (long long)(16 * p) * ATTH);

    const int NITER = NC / GBK;   // 16
    int cur = 0;
    #pragma unroll 1
    for (int it = 0; it < NITER; ++it) {
        unsigned* Ac = sA + cur * GBK * ASTR;
        unsigned* Bc = sB + cur * GBK * BSTR;
        #pragma unroll
        for (int p = 0; p < 4; ++p) {
            uint4 v = { f2tf(pa[p].x), f2tf(pa[p].y), f2tf(pa[p].z), f2tf(pa[p].w) };
            *(uint4*)(Ac + (akr + 8 * p) * ASTR + am * 4) = v;
        }
        #pragma unroll
        for (int p = 0; p < 2; ++p) {
            uint4 v = { f2tf(pb[p].x), f2tf(pb[p].y), f2tf(pb[p].z), f2tf(pb[p].w) };
            *(uint4*)(Bc + (br + 16 * p) * BSTR + bc) = v;
        }
        __syncthreads();

        if (it + 1 < NITER) {
            long long k0n = (long long)(it + 1) * GBK;
            #pragma unroll
            for (int p = 0; p < 4; ++p)
                pa[p] = *(const float4*)(Ag + (k0n + 8 * p) * MTOT);
            #pragma unroll
            for (int p = 0; p < 2; ++p)
                pb[p] = *(const float4*)(Bg + (k0n + 16 * p) * ATTH);
        }

        #pragma unroll
        for (int ks = 0; ks < 4; ++ks) {
            const unsigned* Ak  = Ac + (ks * 8 + tig) * ASTR + wm_ + grp;
            const unsigned* Ak4 = Ak + 4 * ASTR;
            unsigned a0[4] = { Ak[0],  Ak[8],  Ak4[0],  Ak4[8]  };
            unsigned a1[4] = { Ak[16], Ak[24], Ak4[16], Ak4[24] };
            const unsigned* Bk  = Bc + (ks * 8 + tig) * BSTR + wn_ + grp;
            const unsigned* Bk4 = Bk + 4 * BSTR;
            #pragma unroll
            for (int nt = 0; nt < 4; ++nt) {
                unsigned b0 = Bk[nt * 8], b1 = Bk4[nt * 8];
                MMA_TF32(d[0][nt], a0, b0, b1);
                MMA_TF32(d[1][nt], a1, b0, b1);
            }
        }
        cur ^= 1;
    }

    #pragma unroll
    for (int mt = 0; mt < 2; ++mt) {
        float p0 = 0.0f, p1 = 0.0f;
        #pragma unroll
        for (int nt = 0; nt < 4; ++nt) {
            int n0 = wn_ + nt * 8 + 2 * tig;
            float b10 = s_b1[n0], b11 = s_b1[n0 + 1];
            float w20 = s_w2[n0], w21 = s_w2[n0 + 1];
            p0 += fmaxf(d[mt][nt][0] + b10, 0.0f) * w20
                + fmaxf(d[mt][nt][1] + b11, 0.0f) * w21;
            p1 += fmaxf(d[mt][nt][2] + b10, 0.0f) * w20
                + fmaxf(d[mt][nt][3] + b11, 0.0f) * w21;
        }
        p0 += __shfl_xor_sync(0xffffffffu, p0, 1);
        p0 += __shfl_xor_sync(0xffffffffu, p0, 2);
        p1 += __shfl_xor_sync(0xffffffffu, p1, 1);
        p1 += __shfl_xor_sync(0xffffffffu, p1, 2);
        if (tig == 0) {
            atomicAdd(&g_att[mbase + wm_ + mt * 16 + grp], p0);
            atomicAdd(&g_att[mbase + wm_ + mt * 16 + grp + 8], p1);
        }
    }
}

// ============================================================
// Kernel 5: fused softmax + weighted mean + partial class dots.
// ============================================================
__global__ void wm_kernel(const float* __restrict__ Wh,
                          const float* __restrict__ ba2,
                          float* __restrict__ out) {
    int b = blockIdx.y, cg = blockIdx.x, t = threadIdx.x;
    int lane = t & 31, w = t >> 5;
    __shared__ float satt[NSG];
    __shared__ float red[4];

    float v = g_att[b * NSG + t] + ba2[0];
    float m = v;
    #pragma unroll
    for (int o = 16; o > 0; o >>= 1) m = fmaxf(m, __shfl_xor_sync(0xffffffffu, m, o));
    if (lane == 0) red[w] = m;
    __syncthreads();
    m = fmaxf(fmaxf(red[0], red[1]), fmaxf(red[2], red[3]));
    float e = expf(v - m);
    float s = e;
    #pragma unroll
    for (int o = 16; o > 0; o >>= 1) s += __shfl_xor_sync(0xffffffffu, s, o);
    __syncthreads();
    if (lane == 0) red[w] = s;
    __syncthreads();
    s = red[0] + red[1] + red[2] + red[3];
    satt[t] = e / s;
    __syncthreads();

    int c = cg * 128 + t;
    float wm = 0.0f;
    const float* mp = g_meansT + (long long)c * MTOT + b * NSG;
    #pragma unroll 8
    for (int sg = 0; sg < NSG; ++sg) wm += satt[sg] * mp[sg];

    const float* whr = Wh + (long long)c * NCLS;
    #pragma unroll 1
    for (int cls = 0; cls < NCLS; ++cls) {
        float p = wm * whr[cls];
        #pragma unroll
        for (int o = 16; o > 0; o >>= 1) p += __shfl_xor_sync(0xffffffffu, p, o);
        if (lane == 0) atomicAdd(&out[b * NCLS + cls], p);
    }
}

// ============================================================
// Kernel 6: BCE-with-logits loss, mean over all 608 elements.
// ============================================================
__global__ void loss_kernel(const float* __restrict__ target,
                            float* __restrict__ out, int out_size) {
    const int n = NB * NCLS;   // 608
    int t = threadIdx.x;
    float v = 0.0f;
    if (t < n) {
        float l = out[t];
        float tg = target[t];
        v = fmaxf(l, 0.0f) - l * tg + log1pf(expf(-fabsf(l)));
    }
    __shared__ float red[32];
    int lane = t & 31, warp = t >> 5;
    #pragma unroll
    for (int o = 16; o > 0; o >>= 1) v += __shfl_xor_sync(0xffffffffu, v, o);
    if (lane == 0) red[warp] = v;
    __syncthreads();
    if (t < 32) {
        float s = (t < 20) ? red[t] : 0.0f;
        #pragma unroll
        for (int o = 16; o > 0; o >>= 1) s += __shfl_xor_sync(0xffffffffu, s, o);
        if (t == 0) out[out_size - 1] = s / (float)n;
    }
}

// ============================================================
extern "C" void kernel_launch(void* const* d_in, const int* in_sizes, int n_in,
                              void* d_out, int out_size) {
    const float* x      = (const float*)d_in[0];
    const int*   mask   = (const int*)d_in[1];
    const float* target = (const float*)d_in[2];
    const float* Wa1    = (const float*)d_in[3];
    const float* ba1    = (const float*)d_in[4];
    const float* Wa2    = (const float*)d_in[5];
    const float* ba2    = (const float*)d_in[6];
    const float* Wh     = (const float*)d_in[7];
    const float* bh     = (const float*)d_in[8];
    float* out = (float*)d_out;

    cudaFuncSetAttribute(seg_kernel,
                         cudaFuncAttributeMaxDynamicSharedMemorySize, SEG_SMEM);
    cudaFuncSetAttribute(att_gemm_kernel,
                         cudaFuncAttributeMaxDynamicSharedMemorySize, GEMM_SMEM);

    prep_sort_kernel<<<dim3(NTILE, NB), 128>>>(mask);                    // idx 0
    invc_kernel<<<NB, 256>>>(bh, out);                                   // idx 1
    seg_kernel<<<dim3(16, NB), 512, SEG_SMEM>>>(x);                      // idx 2
    att_gemm_kernel<<<dim3(ATTH / GBN, MTOT / GBM), 256, GEMM_SMEM>>>(Wa1, ba1, Wa2); // idx 3 (profiled)
    wm_kernel<<<dim3(4, NB), 128>>>(Wh, ba2, out);                       // idx 4
    loss_kernel<<<1, 640>>>(target, out, out_size);                      // idx 5
}